// round 2
// baseline (speedup 1.0000x reference)
#include <cuda_runtime.h>
#include <cstdint>

#define BB 32
#define AA 8400
#define NCH 84
#define NCLS 80
#define KK 1024
#define GG 32
#define NSUP 16
#define MAXDET 300

// ---------------- scratch (static device globals; no allocation) ----------------
__device__ float    g_conf[BB * AA];
__device__ int      g_cls[BB * AA];
__device__ float    g_confk[BB * KK];
__device__ int      g_clsk[BB * KK];
__device__ float4   g_box[BB * KK];     // unshifted (match)
__device__ float4   g_sbox[BB * KK];    // class-shifted (NMS)
__device__ unsigned g_mask[BB * KK * 32];
__device__ unsigned g_keep[BB * 32];

// IEEE-exact IoU matching jnp order: inter / ((area_a + area_b) - inter + 1e-9)
__device__ __forceinline__ float iou_rn(float4 A_, float4 B_) {
    float ltx = fmaxf(A_.x, B_.x), lty = fmaxf(A_.y, B_.y);
    float rbx = fminf(A_.z, B_.z), rby = fminf(A_.w, B_.w);
    float w = fmaxf(__fsub_rn(rbx, ltx), 0.0f);
    float h = fmaxf(__fsub_rn(rby, lty), 0.0f);
    float inter = __fmul_rn(w, h);
    float aa = __fmul_rn(__fsub_rn(A_.z, A_.x), __fsub_rn(A_.w, A_.y));
    float ab = __fmul_rn(__fsub_rn(B_.z, B_.x), __fsub_rn(B_.w, B_.y));
    float den = __fadd_rn(__fsub_rn(__fadd_rn(aa, ab), inter), 1e-9f);
    return __fdiv_rn(inter, den);
}

// -------- K1: decode conf/cls per anchor --------
__global__ void k_decode(const float* __restrict__ preds) {
    int a = blockIdx.x * 256 + threadIdx.x;
    int b = blockIdx.y;
    if (a >= AA) return;
    const float* p = preds + (size_t)b * NCH * AA;
    float best = p[4 * AA + a];
    int bi = 0;
#pragma unroll 8
    for (int c = 1; c < NCLS; c++) {
        float s = p[(4 + c) * AA + a];
        if (s > best) { best = s; bi = c; }
    }
    g_conf[b * AA + a] = (best > 0.25f) ? best : 0.0f;
    g_cls[b * AA + a] = bi;
}

// -------- K2: per-image top-K radix select + bitonic sort + box build --------
__global__ __launch_bounds__(1024, 1) void k_select(const float* __restrict__ preds) {
    extern __shared__ unsigned long long ss[];   // KK sorted keys (8 KB)
    __shared__ unsigned hist[256];
    __shared__ unsigned long long sh_pref;
    __shared__ int sh_m;
    __shared__ int sh_cnt;

    int b = blockIdx.x, tid = threadIdx.x;

    // Build distinct 64-bit keys in registers: conf bits (monotone for conf>=0) | (~idx)
    unsigned long long rk[9];
#pragma unroll
    for (int e0 = 0; e0 < 9; e0++) {
        int e = e0 * 1024 + tid;
        unsigned long long key = 0ull;
        if (e < AA) {
            unsigned cb = __float_as_uint(g_conf[b * AA + e]);
            key = ((unsigned long long)cb << 32) | (0xFFFFFFFFu - (unsigned)e);
        }
        rk[e0] = key;
    }
    if (tid == 0) { sh_pref = 0ull; sh_m = KK; sh_cnt = 0; }
    __syncthreads();

    // 8 passes, 8-bit digits, MSB first
    for (int p = 0; p < 8; p++) {
        int shift = 56 - 8 * p;
        if (tid < 256) hist[tid] = 0u;
        __syncthreads();
        unsigned long long pref = sh_pref;
#pragma unroll
        for (int e0 = 0; e0 < 9; e0++) {
            int e = e0 * 1024 + tid;
            int digit = 256;
            if (e < AA) {
                unsigned long long key = rk[e0];
                bool match = (p == 0) || (((key ^ pref) >> (shift + 8)) == 0ull);
                if (match) digit = (int)((key >> shift) & 255ull);
            }
            unsigned mm = __match_any_sync(0xFFFFFFFFu, digit);
            if (digit < 256) {
                int leader = __ffs(mm) - 1;
                if ((tid & 31) == leader) atomicAdd(&hist[digit], (unsigned)__popc(mm));
            }
        }
        __syncthreads();
        if (tid == 0) {
            int m = sh_m, cum = 0;
            unsigned long long pr = sh_pref;
            for (int d = 255; d >= 0; d--) {
                int c = (int)hist[d];
                cum += c;
                if (cum >= m) {
                    sh_m = m - (cum - c);
                    sh_pref = pr | ((unsigned long long)d << shift);
                    break;
                }
            }
        }
        __syncthreads();
    }
    unsigned long long T = sh_pref;   // exact 1024th-largest key (keys distinct)

    // compact (order irrelevant; sorted next)
#pragma unroll
    for (int e0 = 0; e0 < 9; e0++) {
        int e = e0 * 1024 + tid;
        if (e < AA && rk[e0] >= T) {
            int pos = atomicAdd(&sh_cnt, 1);
            ss[pos] = rk[e0];
        }
    }
    __syncthreads();

    // bitonic sort descending, 1024 elements, 1024 threads
    for (int k = 2; k <= KK; k <<= 1) {
        for (int j = k >> 1; j > 0; j >>= 1) {
            int ixj = tid ^ j;
            if (ixj > tid) {
                unsigned long long x = ss[tid], y = ss[ixj];
                bool desc = ((tid & k) == 0);
                if (desc ? (x < y) : (x > y)) { ss[tid] = y; ss[ixj] = x; }
            }
            __syncthreads();
        }
    }

    // epilogue: decode boxes for the 1024 selected
    {
        unsigned long long key = ss[tid];
        float conf = __uint_as_float((unsigned)(key >> 32));
        unsigned a = 0xFFFFFFFFu - (unsigned)(key & 0xFFFFFFFFull);
        int cls = g_cls[b * AA + a];
        const float* p = preds + (size_t)b * NCH * AA;
        float cx = p[a], cy = p[AA + a], w = p[2 * AA + a], h = p[3 * AA + a];
        float hw = __fmul_rn(w, 0.5f), hh = __fmul_rn(h, 0.5f);
        float x1 = __fsub_rn(cx, hw), y1 = __fsub_rn(cy, hh);
        float x2 = __fadd_rn(cx, hw), y2 = __fadd_rn(cy, hh);
        float sft = __fmul_rn((float)cls, 7680.0f);
        int o = b * KK + tid;
        g_confk[o] = conf;
        g_clsk[o] = cls;
        g_box[o] = make_float4(x1, y1, x2, y2);
        g_sbox[o] = make_float4(__fadd_rn(x1, sft), __fadd_rn(y1, sft),
                                __fadd_rn(x2, sft), __fadd_rn(y2, sft));
    }
}

// -------- K3: suppression bitmask (i-tile of 32 rows per block) --------
__global__ void k_mask() {
    __shared__ float4 sb[KK];
    int b = blockIdx.y, tile = blockIdx.x, tid = threadIdx.x;
    for (int j = tid; j < KK; j += 256) sb[j] = g_sbox[b * KK + j];
    __syncthreads();
#pragma unroll
    for (int q = 0; q < 4; q++) {
        int word = q * 256 + tid;          // 0..1023 = (il, w)
        int il = word >> 5, w = word & 31;
        int i = tile * 32 + il;
        unsigned bits = 0u;
        if (w * 32 < i) {
            float4 bi = sb[i];
            int jmax = min(32, i - w * 32);
            for (int jj = 0; jj < jmax; jj++) {
                float v = iou_rn(bi, sb[w * 32 + jj]);
                if (v > 0.45f) bits |= 1u << jj;
            }
        }
        g_mask[((size_t)b * KK + i) * 32 + w] = bits;
    }
}

// -------- K4: sequential NMS scan (warp 0 per image, mask staged in smem) --------
__global__ __launch_bounds__(1024, 1) void k_nms() {
    extern __shared__ unsigned sm[];   // 32768 words = 128 KB
    __shared__ unsigned sval[32];
    int b = blockIdx.x, tid = threadIdx.x;
    for (int w = tid; w < KK * 32; w += 1024) sm[w] = g_mask[(size_t)b * KK * 32 + w];
    {
        bool v = g_confk[b * KK + tid] > 0.0f;
        unsigned bal = __ballot_sync(0xFFFFFFFFu, v);
        if ((tid & 31) == 0) sval[tid >> 5] = bal;
    }
    __syncthreads();
    if (tid < 32) {
        int lane = tid;
        unsigned keep = 0u, fin = 0u;
        int cnt = 0;
        unsigned row = sm[lane];
        for (int i = 0; i < KK; i++) {
            unsigned nxt = (i + 1 < KK) ? sm[(i + 1) * 32 + lane] : 0u;
            bool sup = __any_sync(0xFFFFFFFFu, (row & keep) != 0u);
            bool v = (sval[i >> 5] >> (i & 31)) & 1u;
            if (v && !sup) {
                cnt++;
                if (lane == (i >> 5)) {
                    keep |= 1u << (i & 31);
                    if (cnt <= MAXDET) fin |= 1u << (i & 31);
                }
            }
            row = nxt;
        }
        g_keep[b * 32 + lane] = fin;
    }
}

// -------- K5: GT matching + stats --------
__global__ __launch_bounds__(128, 1) void k_match(const float* __restrict__ gt_b,
                                                  const int* __restrict__ gt_c,
                                                  const unsigned* __restrict__ gt_m,
                                                  const int* __restrict__ c2s,
                                                  float* __restrict__ out) {
    __shared__ float   sconf[KK];
    __shared__ int     scls[KK];
    __shared__ float4  sbox[KK];
    __shared__ unsigned char spv[KK];
    __shared__ float   sbv[GG];
    __shared__ int     sbi[GG];
    __shared__ float   scat[NCLS];
    __shared__ float   ssup[NSUP];
    __shared__ int     s_npred;
    __shared__ float4  sgt[GG];
    __shared__ int     sgc[GG];
    __shared__ int     sgm[GG];

    int b = blockIdx.x, tid = threadIdx.x;
    if (tid == 0) s_npred = 0;
    if (tid < NCLS) scat[tid] = 0.0f;
    if (tid >= NCLS && tid < NCLS + NSUP) ssup[tid - NCLS] = 0.0f;
    if (tid < GG) {
        const float* gb = gt_b + ((size_t)b * GG + tid) * 4;
        sgt[tid] = make_float4(gb[0], gb[1], gb[2], gb[3]);
        sgc[tid] = gt_c[b * GG + tid];
        sgm[tid] = (gt_m[b * GG + tid] != 0u) ? 1 : 0;
    }
    int npl = 0;
    for (int r = tid; r < KK; r += 128) {
        float c = g_confk[b * KK + r];
        sconf[r] = c;
        scls[r] = g_clsk[b * KK + r];
        sbox[r] = g_box[b * KK + r];
        bool keep = (g_keep[b * 32 + (r >> 5)] >> (r & 31)) & 1u;
        bool pv = keep && (c > 0.5f);
        spv[r] = pv ? 1 : 0;
        npl += pv ? 1 : 0;
    }
    atomicAdd(&s_npred, npl);
    __syncthreads();

    int warp = tid >> 5, lane = tid & 31;
#pragma unroll
    for (int q = 0; q < 8; q++) {
        int g = warp * 8 + q;
        float4 gb = sgt[g];
        int gc = sgc[g];
        float bv = -1.0f;
        int bi = 0;
        for (int r = lane; r < KK; r += 32) {
            if (spv[r] && scls[r] == gc) {
                float v = iou_rn(sbox[r], gb);
                if (v > bv) { bv = v; bi = r; }   // first-occurrence within lane
            }
        }
#pragma unroll
        for (int off = 16; off; off >>= 1) {
            float ov = __shfl_down_sync(0xFFFFFFFFu, bv, off);
            int   oi = __shfl_down_sync(0xFFFFFFFFu, bi, off);
            if (ov > bv || (ov == bv && oi < bi)) { bv = ov; bi = oi; }
        }
        if (lane == 0) { sbv[g] = bv; sbi[g] = bi; }
    }
    __syncthreads();
    if (tid < GG) {
        float gm = (float)sgm[tid];
        atomicAdd(&scat[sgc[tid]], gm);
        atomicAdd(&ssup[c2s[sgc[tid]]], gm);
    }
    __syncthreads();
    if (tid == 0) {
        int n_gt = 0, n_hit = 0;
        float si = 0.0f, sc = 0.0f;
        for (int g = 0; g < GG; g++) {
            n_gt += sgm[g];
            bool hit = (sbv[g] > 0.6f) && (sgm[g] != 0);
            if (hit) { n_hit++; si = __fadd_rn(si, sbv[g]); sc = __fadd_rn(sc, sconf[sbi[g]]); }
        }
        float r0, r1, r2, r3, r4;
        if (n_gt == 0) {
            if (s_npred == 0) { r0 = 1.0f; r1 = 1.0f; r2 = -1.0f; r3 = -1.0f; r4 = 1.0f; }
            else             { r0 = 0.0f; r1 = 1.0f; r2 = -2.0f; r3 = -2.0f; r4 = 0.0f; }
        } else {
            float fh = (float)n_hit;
            r0 = __fdiv_rn(si, fmaxf(fh, 1.0f));
            r1 = (n_hit > 0) ? __fdiv_rn(sc, fmaxf(fh, 1.0f)) : 1.0f;
            float bc = -1.0f; int bci = 0;
            for (int c = 0; c < NCLS; c++) if (scat[c] > bc) { bc = scat[c]; bci = c; }
            r2 = (float)bci;
            float bs = -1.0f; int bsi = 0;
            for (int s = 0; s < NSUP; s++) if (ssup[s] > bs) { bs = ssup[s]; bsi = s; }
            r3 = (float)bsi;
            r4 = __fdiv_rn(fh, fmaxf((float)n_gt, 1.0f));
        }
        out[b * 5 + 0] = r0;
        out[b * 5 + 1] = r1;
        out[b * 5 + 2] = r2;
        out[b * 5 + 3] = r3;
        out[b * 5 + 4] = r4;
    }
}

extern "C" void kernel_launch(void* const* d_in, const int* in_sizes, int n_in,
                              void* d_out, int out_size) {
    const float*    preds = (const float*)d_in[0];
    const float*    gtb   = (const float*)d_in[1];
    const int*      gtc   = (const int*)d_in[2];
    const unsigned* gtm   = (const unsigned*)d_in[3];  // bool serialized as 32-bit words (nonzero = true)
    const int*      c2s   = (const int*)d_in[4];
    float* out = (float*)d_out;

    cudaFuncSetAttribute(k_nms, cudaFuncAttributeMaxDynamicSharedMemorySize, KK * 32 * 4);

    dim3 g1((AA + 255) / 256, BB);
    k_decode<<<g1, 256>>>(preds);
    k_select<<<BB, 1024, KK * 8>>>(preds);
    k_mask<<<dim3(32, BB), 256>>>();
    k_nms<<<BB, 1024, KK * 32 * 4>>>();
    k_match<<<BB, 128>>>(gtb, gtc, gtm, c2s, out);
}

// round 3
// speedup vs baseline: 1.2979x; 1.2979x over previous
#include <cuda_runtime.h>
#include <cstdint>

#define BB 32
#define AA 8400
#define A4 2100
#define NCH 84
#define NCLS 80
#define KK 1024
#define GG 32
#define NSUP 16
#define MAXDET 300

// ---------------- scratch (static device globals; no allocation) ----------------
__device__ __align__(16) float    g_conf[BB * AA];
__device__ __align__(16) int      g_cls[BB * AA];
__device__ float    g_confk[BB * KK];
__device__ int      g_clsk[BB * KK];
__device__ float4   g_box[BB * KK];     // unshifted (match)
__device__ float4   g_sbox[BB * KK];    // class-shifted (NMS)
__device__ __align__(16) unsigned g_mask[BB * KK * 32];
__device__ unsigned g_keep[BB * 32];

// IEEE-exact IoU matching jnp order: inter / ((area_a + area_b) - inter + 1e-9)
__device__ __forceinline__ float iou_rn(float4 A_, float4 B_) {
    float ltx = fmaxf(A_.x, B_.x), lty = fmaxf(A_.y, B_.y);
    float rbx = fminf(A_.z, B_.z), rby = fminf(A_.w, B_.w);
    float w = fmaxf(__fsub_rn(rbx, ltx), 0.0f);
    float h = fmaxf(__fsub_rn(rby, lty), 0.0f);
    float inter = __fmul_rn(w, h);
    float aa = __fmul_rn(__fsub_rn(A_.z, A_.x), __fsub_rn(A_.w, A_.y));
    float ab = __fmul_rn(__fsub_rn(B_.z, B_.x), __fsub_rn(B_.w, B_.y));
    float den = __fadd_rn(__fsub_rn(__fadd_rn(aa, ab), inter), 1e-9f);
    return __fdiv_rn(inter, den);
}

// -------- K1: decode conf/cls, 4 anchors per thread (float4) --------
__global__ void k_decode(const float* __restrict__ preds) {
    int t = blockIdx.x * 256 + threadIdx.x;
    int b = blockIdx.y;
    if (t >= A4) return;
    const float4* p = (const float4*)(preds + (size_t)b * NCH * AA);
    float4 best = p[4 * A4 + t];
    int bx = 0, by = 0, bz = 0, bw = 0;
#pragma unroll 8
    for (int c = 1; c < NCLS; c++) {
        float4 s = p[(4 + c) * A4 + t];
        if (s.x > best.x) { best.x = s.x; bx = c; }
        if (s.y > best.y) { best.y = s.y; by = c; }
        if (s.z > best.z) { best.z = s.z; bz = c; }
        if (s.w > best.w) { best.w = s.w; bw = c; }
    }
    best.x = (best.x > 0.25f) ? best.x : 0.0f;
    best.y = (best.y > 0.25f) ? best.y : 0.0f;
    best.z = (best.z > 0.25f) ? best.z : 0.0f;
    best.w = (best.w > 0.25f) ? best.w : 0.0f;
    ((float4*)g_conf)[b * A4 + t] = best;
    ((int4*)g_cls)[b * A4 + t] = make_int4(bx, by, bz, bw);
}

// -------- K2: per-image top-K radix select + hybrid bitonic sort --------
__global__ __launch_bounds__(1024, 1) void k_select(const float* __restrict__ preds) {
    __shared__ unsigned long long ss[KK];
    __shared__ int hist[256];
    __shared__ int s_cum[257];
    __shared__ int wsum[8];
    __shared__ unsigned long long sh_pref;
    __shared__ int sh_m;
    __shared__ int sh_cnt;

    int b = blockIdx.x, tid = threadIdx.x, lane = tid & 31;

    // distinct 64-bit keys: conf bits (monotone for conf>=0) | (~idx)
    unsigned long long rk[9];
#pragma unroll
    for (int e0 = 0; e0 < 9; e0++) {
        int e = e0 * 1024 + tid;
        unsigned long long key = 0ull;
        if (e < AA) {
            unsigned cb = __float_as_uint(g_conf[b * AA + e]);
            key = ((unsigned long long)cb << 32) | (0xFFFFFFFFu - (unsigned)e);
        }
        rk[e0] = key;
    }
    if (tid == 0) { sh_pref = 0ull; sh_m = KK; sh_cnt = 0; }
    if (tid == 256) s_cum[256] = 0;
    __syncthreads();

    for (int p = 0; p < 8; p++) {
        if (tid < 256) hist[tid] = 0;
        __syncthreads();
        int shift = 56 - 8 * p;
        unsigned long long pref = sh_pref;
        int m = sh_m;
#pragma unroll
        for (int e0 = 0; e0 < 9; e0++) {
            int e = e0 * 1024 + tid;
            int digit = 256;
            if (e < AA) {
                unsigned long long key = rk[e0];
                bool match = (p == 0) || (((key ^ pref) >> (shift + 8)) == 0ull);
                if (match) digit = (int)((key >> shift) & 255ull);
            }
            unsigned mm = __match_any_sync(0xFFFFFFFFu, digit);
            if (digit < 256 && lane == (__ffs(mm) - 1)) atomicAdd(&hist[digit], __popc(mm));
        }
        __syncthreads();
        // parallel suffix scan over 256 bins
        int h = 0;
        if (tid < 256) {
            h = hist[tid];
#pragma unroll
            for (int off = 1; off < 32; off <<= 1) {
                int n = __shfl_down_sync(0xFFFFFFFFu, h, off);
                if (lane + off < 32) h += n;
            }
            if (lane == 0) wsum[tid >> 5] = h;
        }
        __syncthreads();
        if (tid < 256) {
            int w = tid >> 5, add = 0;
#pragma unroll
            for (int w2 = 0; w2 < 8; w2++) if (w2 > w) add += wsum[w2];
            s_cum[tid] = h + add;
        }
        __syncthreads();
        if (tid < 256) {
            int cd = s_cum[tid], cn = s_cum[tid + 1];
            if (cd >= m && cn < m) {
                sh_pref = pref | ((unsigned long long)tid << shift);
                sh_m = m - cn;
            }
        }
        __syncthreads();
    }
    unsigned long long T = sh_pref;   // exact 1024th-largest key (keys distinct)

    // warp-aggregated compaction (order irrelevant; sorted next)
#pragma unroll
    for (int e0 = 0; e0 < 9; e0++) {
        int e = e0 * 1024 + tid;
        bool sel = (e < AA) && (rk[e0] >= T);
        unsigned bal = __ballot_sync(0xFFFFFFFFu, sel);
        if (bal) {
            int basep = 0;
            if (lane == 0) basep = atomicAdd(&sh_cnt, __popc(bal));
            basep = __shfl_sync(0xFFFFFFFFu, basep, 0);
            if (sel) ss[basep + __popc(bal & ((1u << lane) - 1u))] = rk[e0];
        }
    }
    __syncthreads();

    // hybrid bitonic sort descending (smem for j>=32, shfl for j<32)
    unsigned long long val = ss[tid];
    for (int k = 2; k <= KK; k <<= 1) {
        for (int j = k >> 1; j >= 32; j >>= 1) {
            __syncthreads();
            ss[tid] = val;
            __syncthreads();
            unsigned long long other = ss[tid ^ j];
            bool lower = (tid & j) == 0, desc = (tid & k) == 0;
            unsigned long long mx = val > other ? val : other;
            unsigned long long mn = val > other ? other : val;
            val = (lower == desc) ? mx : mn;
        }
        for (int j = ((k >> 1) < 32 ? (k >> 1) : 16); j >= 1; j >>= 1) {
            unsigned long long other = __shfl_xor_sync(0xFFFFFFFFu, val, j);
            bool lower = (tid & j) == 0, desc = (tid & k) == 0;
            unsigned long long mx = val > other ? val : other;
            unsigned long long mn = val > other ? other : val;
            val = (lower == desc) ? mx : mn;
        }
    }

    // epilogue: decode boxes for the 1024 selected (keys still in registers)
    {
        float conf = __uint_as_float((unsigned)(val >> 32));
        unsigned a = 0xFFFFFFFFu - (unsigned)(val & 0xFFFFFFFFull);
        int cls = g_cls[b * AA + a];
        const float* p = preds + (size_t)b * NCH * AA;
        float cx = p[a], cy = p[AA + a], w = p[2 * AA + a], h = p[3 * AA + a];
        float hw = __fmul_rn(w, 0.5f), hh = __fmul_rn(h, 0.5f);
        float x1 = __fsub_rn(cx, hw), y1 = __fsub_rn(cy, hh);
        float x2 = __fadd_rn(cx, hw), y2 = __fadd_rn(cy, hh);
        float sft = __fmul_rn((float)cls, 7680.0f);
        int o = b * KK + tid;
        g_confk[o] = conf;
        g_clsk[o] = cls;
        g_box[o] = make_float4(x1, y1, x2, y2);
        g_sbox[o] = make_float4(__fadd_rn(x1, sft), __fadd_rn(y1, sft),
                                __fadd_rn(x2, sft), __fadd_rn(y2, sft));
    }
}

// -------- K3: suppression bitmask; skip fdiv when inter==0 --------
__global__ void k_mask() {
    __shared__ float4 sb[KK];
    __shared__ float  sa[KK];
    int b = blockIdx.y, tile = blockIdx.x, tid = threadIdx.x;
    for (int j = tid; j < KK; j += 256) {
        float4 v = g_sbox[b * KK + j];
        sb[j] = v;
        sa[j] = __fmul_rn(__fsub_rn(v.z, v.x), __fsub_rn(v.w, v.y));
    }
    __syncthreads();
#pragma unroll
    for (int q = 0; q < 4; q++) {
        int word = q * 256 + tid;          // (il, w)
        int il = word >> 5, w = word & 31;
        int i = tile * 32 + il;
        unsigned bits = 0u;
        if (w * 32 < i) {
            float4 bi = sb[i];
            float ai = sa[i];
            int jmax = min(32, i - w * 32);
            for (int jj = 0; jj < jmax; jj++) {
                int j = w * 32 + jj;
                float4 bj = sb[j];
                float ltx = fmaxf(bi.x, bj.x), lty = fmaxf(bi.y, bj.y);
                float rbx = fminf(bi.z, bj.z), rby = fminf(bi.w, bj.w);
                float wd = fmaxf(__fsub_rn(rbx, ltx), 0.0f);
                float ht = fmaxf(__fsub_rn(rby, lty), 0.0f);
                float inter = __fmul_rn(wd, ht);
                if (inter > 0.0f) {
                    float den = __fadd_rn(__fsub_rn(__fadd_rn(ai, sa[j]), inter), 1e-9f);
                    if (__fdiv_rn(inter, den) > 0.45f) bits |= 1u << jj;
                }
            }
        }
        g_mask[((size_t)b * KK + i) * 32 + w] = bits;
    }
}

// -------- K4: chunked NMS scan: 32 candidates resolved per step --------
__global__ __launch_bounds__(1024, 1) void k_nms() {
    extern __shared__ unsigned sm[];   // 32768 words = 128 KB
    __shared__ unsigned sval[32];
    int b = blockIdx.x, tid = threadIdx.x;
    {
        const uint4* src = (const uint4*)(g_mask + (size_t)b * KK * 32);
        uint4* dst = (uint4*)sm;
#pragma unroll
        for (int q = 0; q < 8; q++) dst[q * 1024 + tid] = src[q * 1024 + tid];
        bool v = g_confk[b * KK + tid] > 0.0f;
        unsigned bal = __ballot_sync(0xFFFFFFFFu, v);
        if ((tid & 31) == 0) sval[tid >> 5] = bal;
    }
    __syncthreads();
    if (tid < 32) {
        int lane = tid;
        unsigned keepw = 0u, finw = 0u;
        int cnt = 0;
        for (int c = 0; c < 32; c++) {
            // bit i: row (c*32+i) suppressed by a kept box from earlier chunks
            unsigned pre = 0u;
            const unsigned* base = sm + (c * 32) * 32 + lane;
            if (__any_sync(0xFFFFFFFFu, keepw != 0u)) {
#pragma unroll
                for (int i = 0; i < 32; i++)
                    if (base[i * 32] & keepw) pre |= 1u << i;
            }
            unsigned prevSup = __reduce_or_sync(0xFFFFFFFFu, pre);
            unsigned tri = sm[(c * 32 + lane) * 32 + c];   // intra-chunk triangle row
            unsigned vwd = sval[c];
            unsigned kc = 0u;
#pragma unroll
            for (int il = 0; il < 32; il++) {
                unsigned t = __shfl_sync(0xFFFFFFFFu, tri, il);
                bool sup = ((prevSup >> il) & 1u) || ((t & kc) != 0u);
                if (((vwd >> il) & 1u) && !sup) kc |= 1u << il;
            }
            if (lane == c) {
                keepw = kc;
                unsigned f = 0u;
                int allowed = MAXDET - cnt;
                if (allowed > 0) {
                    if (__popc(kc) <= allowed) f = kc;
                    else {
                        unsigned tmp = kc;
                        for (int t2 = 0; t2 < allowed; t2++) { f |= tmp & (0u - tmp); tmp &= tmp - 1u; }
                    }
                }
                finw = f;
            }
            cnt += __popc(kc);   // kc uniform across lanes
        }
        g_keep[b * 32 + lane] = finw;
    }
}

// -------- K5: GT matching on compacted prediction list --------
__global__ __launch_bounds__(256, 1) void k_match(const float* __restrict__ gt_b,
                                                  const int* __restrict__ gt_c,
                                                  const unsigned* __restrict__ gt_m,
                                                  const int* __restrict__ c2s,
                                                  float* __restrict__ out) {
    __shared__ float   sconf[KK];
    __shared__ float4  cbox[KK];
    __shared__ int     ccls[KK];
    __shared__ int     cidx[KK];
    __shared__ int     wtot[8];
    __shared__ int     s_np;
    __shared__ float   sbv[GG];
    __shared__ int     sbi[GG];
    __shared__ float   scat[NCLS];
    __shared__ float   ssup[NSUP];
    __shared__ float4  sgt[GG];
    __shared__ int     sgc[GG];
    __shared__ int     sgm[GG];

    int b = blockIdx.x, tid = threadIdx.x, lane = tid & 31, warp = tid >> 5;
    if (tid < NCLS) scat[tid] = 0.0f;
    if (tid >= NCLS && tid < NCLS + NSUP) ssup[tid - NCLS] = 0.0f;
    if (tid < GG) {
        const float* gb = gt_b + ((size_t)b * GG + tid) * 4;
        sgt[tid] = make_float4(gb[0], gb[1], gb[2], gb[3]);
        sgc[tid] = gt_c[b * GG + tid];
        sgm[tid] = (gt_m[b * GG + tid] != 0u) ? 1 : 0;
    }
    // phase A: rows tid*4 .. tid*4+3 (contiguous -> stable compaction)
    unsigned kw = g_keep[b * 32 + (tid >> 3)];
    bool pv[4];
    int cnt4 = 0;
#pragma unroll
    for (int q = 0; q < 4; q++) {
        int r = tid * 4 + q;
        float c = g_confk[b * KK + r];
        sconf[r] = c;
        bool p = (((kw >> (r & 31)) & 1u) != 0u) && (c > 0.5f);
        pv[q] = p;
        cnt4 += p ? 1 : 0;
    }
    int incl = cnt4;
#pragma unroll
    for (int off = 1; off < 32; off <<= 1) {
        int n = __shfl_up_sync(0xFFFFFFFFu, incl, off);
        if (lane >= off) incl += n;
    }
    if (lane == 31) wtot[warp] = incl;
    __syncthreads();
    int basew = 0;
#pragma unroll
    for (int w2 = 0; w2 < 8; w2++) if (w2 < warp) basew += wtot[w2];
    int pos = basew + incl - cnt4;
#pragma unroll
    for (int q = 0; q < 4; q++) {
        if (pv[q]) {
            int r = tid * 4 + q;
            cbox[pos] = g_box[b * KK + r];
            ccls[pos] = g_clsk[b * KK + r];
            cidx[pos] = r;
            pos++;
        }
    }
    if (tid == 255) s_np = basew + incl;
    __syncthreads();
    int n_pv = s_np;

    // phase B: warp handles 4 GTs over the compacted list
#pragma unroll
    for (int qq = 0; qq < 4; qq++) {
        int g = warp * 4 + qq;
        float4 gb = sgt[g];
        int gc = sgc[g];
        float bv = -1.0f;
        int bi = 0;
        for (int j = lane; j < n_pv; j += 32) {
            if (ccls[j] == gc) {
                float v = iou_rn(cbox[j], gb);
                if (v > bv) { bv = v; bi = cidx[j]; }
            }
        }
#pragma unroll
        for (int off = 16; off; off >>= 1) {
            float ov = __shfl_down_sync(0xFFFFFFFFu, bv, off);
            int   oi = __shfl_down_sync(0xFFFFFFFFu, bi, off);
            if (ov > bv || (ov == bv && oi < bi)) { bv = ov; bi = oi; }
        }
        if (lane == 0) { sbv[g] = bv; sbi[g] = bi; }
    }
    __syncthreads();
    if (tid < GG) {
        float gm = (float)sgm[tid];
        atomicAdd(&scat[sgc[tid]], gm);
        atomicAdd(&ssup[c2s[sgc[tid]]], gm);
    }
    __syncthreads();
    if (tid == 0) {
        int n_gt = 0, n_hit = 0;
        float si = 0.0f, sc = 0.0f;
        for (int g = 0; g < GG; g++) {
            n_gt += sgm[g];
            bool hit = (sbv[g] > 0.6f) && (sgm[g] != 0);
            if (hit) { n_hit++; si = __fadd_rn(si, sbv[g]); sc = __fadd_rn(sc, sconf[sbi[g]]); }
        }
        float r0, r1, r2, r3, r4;
        if (n_gt == 0) {
            if (n_pv == 0) { r0 = 1.0f; r1 = 1.0f; r2 = -1.0f; r3 = -1.0f; r4 = 1.0f; }
            else           { r0 = 0.0f; r1 = 1.0f; r2 = -2.0f; r3 = -2.0f; r4 = 0.0f; }
        } else {
            float fh = (float)n_hit;
            r0 = __fdiv_rn(si, fmaxf(fh, 1.0f));
            r1 = (n_hit > 0) ? __fdiv_rn(sc, fmaxf(fh, 1.0f)) : 1.0f;
            float bc = -1.0f; int bci = 0;
            for (int c = 0; c < NCLS; c++) if (scat[c] > bc) { bc = scat[c]; bci = c; }
            r2 = (float)bci;
            float bs = -1.0f; int bsi = 0;
            for (int s = 0; s < NSUP; s++) if (ssup[s] > bs) { bs = ssup[s]; bsi = s; }
            r3 = (float)bsi;
            r4 = __fdiv_rn(fh, fmaxf((float)n_gt, 1.0f));
        }
        out[b * 5 + 0] = r0;
        out[b * 5 + 1] = r1;
        out[b * 5 + 2] = r2;
        out[b * 5 + 3] = r3;
        out[b * 5 + 4] = r4;
    }
}

extern "C" void kernel_launch(void* const* d_in, const int* in_sizes, int n_in,
                              void* d_out, int out_size) {
    const float*    preds = (const float*)d_in[0];
    const float*    gtb   = (const float*)d_in[1];
    const int*      gtc   = (const int*)d_in[2];
    const unsigned* gtm   = (const unsigned*)d_in[3];
    const int*      c2s   = (const int*)d_in[4];
    float* out = (float*)d_out;

    cudaFuncSetAttribute(k_nms, cudaFuncAttributeMaxDynamicSharedMemorySize, KK * 32 * 4);

    dim3 g1((A4 + 255) / 256, BB);
    k_decode<<<g1, 256>>>(preds);
    k_select<<<BB, 1024>>>(preds);
    k_mask<<<dim3(32, BB), 256>>>();
    k_nms<<<BB, 1024, KK * 32 * 4>>>();
    k_match<<<BB, 256>>>(gtb, gtc, gtm, c2s, out);
}